// round 13
// baseline (speedup 1.0000x reference)
#include <cuda_runtime.h>
#include <cuda_fp16.h>
#include <math.h>
#include <stdint.h>

#define Bz   2
#define Sz   2048
#define Dz   2048
#define Hz   16
#define DHz  128
#define Fz   5504
#define NTz  (Bz*Sz)      // 4096 tokens
#define BHz  (Bz*Hz)      // 32
#define ATTN_SCALE 0.08838834764831845f   // 1/sqrt(128)
#define MASK_NEG  (-60000.0f)             // fp16-representable "-inf"

// ---------------- scratch (device globals; allocation-free) ----------------
__device__ __half g_h1h [(size_t)NTz*Dz];     // rmsnorm out (fp16)
__device__ __half g_qh  [(size_t)NTz*Dz];
__device__ __half g_kh  [(size_t)NTz*Dz];     // k; later vt (transposed V)
__device__ __half g_vh  [(size_t)NTz*Dz];
__device__ __half g_ctxh[(size_t)NTz*Dz];
__device__ float  g_h2  [(size_t)NTz*Dz];     // attn residual (fp32)
__device__ float  g_h3raw[(size_t)NTz*Dz];    // fp32 rmsnorm2 out for router
__device__ __half g_ph  [(size_t)BHz*Sz*Sz];  // fp16 logits -> probs (in-place)
__device__ float  g_rs  [(size_t)BHz*Sz];
__device__ __half g_gateh [(size_t)NTz*Fz];   // expert1 act
__device__ __half g_gate2h[(size_t)NTz*Fz];   // expert2 act
__device__ __half g_uph   [(size_t)NTz*Fz];
__device__ int    g_choice[NTz];
// pre-rounded fp16 weights
#define WR_Q   0
#define WR_K   4194304
#define WR_V   8388608
#define WR_O   12582912
#define WR_E1G 16777216
#define WR_E1U 28049408
#define WR_E1D 39321600
#define WR_E2G 50593792
#define WR_E2U 61865984
#define WR_E2D 73138176
#define WR_TOT 84410368
__device__ __half g_wrh[(size_t)WR_TOT];

// ================= FP16 MMA machinery (unchanged core from R12) =================
#define PITCH_H 40
#define A_HALFS (128*PITCH_H)          // 5120 halfs
#define STAGE_H (2*A_HALFS)            // 10240 halfs = 20480 B
#define NSTAGE 3
#define SMEM_BYTES (NSTAGE*STAGE_H*2)  // 61440 B

__device__ __forceinline__ unsigned sptr(const void* p){ return (unsigned)__cvta_generic_to_shared(p); }
__device__ __forceinline__ void cpa16(unsigned s, const void* g){
    asm volatile("cp.async.cg.shared.global [%0], [%1], 16;\n" :: "r"(s), "l"(g));
}
__device__ __forceinline__ void cpcommit(){ asm volatile("cp.async.commit_group;\n" ::); }
__device__ __forceinline__ void cpwait1(){ asm volatile("cp.async.wait_group 1;\n" ::); }
__device__ __forceinline__ void mma16816(float* c, unsigned a0,unsigned a1,unsigned a2,unsigned a3,
                                         unsigned b0, unsigned b1){
    asm volatile("mma.sync.aligned.m16n8k16.row.col.f32.f16.f16.f32 "
                 "{%0,%1,%2,%3},{%4,%5,%6,%7},{%8,%9},{%0,%1,%2,%3};\n"
                 : "+f"(c[0]),"+f"(c[1]),"+f"(c[2]),"+f"(c[3])
                 : "r"(a0),"r"(a1),"r"(a2),"r"(a3),"r"(b0),"r"(b1));
}

__device__ __forceinline__ void load_tile16(__half* S, const __half* G, int ld, int tid){
    const int r = tid >> 1, cb = (tid & 1) * 16;
    const __half* g = G + (size_t)r * ld + cb;
    unsigned s = sptr(S) + (unsigned)(r * PITCH_H + cb) * 2u;
    cpa16(s, g);
    cpa16(s + 16u, g + 8);
}

__device__ __forceinline__ void compute16(const __half* __restrict__ As, const __half* __restrict__ Bs,
                                          float acc[2][8][4], int warpM, int warpN, int lane){
    const int gi = lane >> 2, tg = lane & 3;
    const int r0 = warpM*32 + gi;
    unsigned a[4][4];
    #pragma unroll
    for (int r = 0; r < 4; r++)
        *(uint4*)a[r] = *(const uint4*)(As + (r0 + r*8)*PITCH_H + tg*8);
    #pragma unroll
    for (int j = 0; j < 8; j++){
        unsigned b[4];
        *(uint4*)b = *(const uint4*)(Bs + (warpN*64 + j*8 + gi)*PITCH_H + tg*8);
        #pragma unroll
        for (int c = 0; c < 2; c++){
            mma16816(acc[0][j], a[0][2*c], a[1][2*c], a[0][2*c+1], a[1][2*c+1], b[2*c], b[2*c+1]);
            mma16816(acc[1][j], a[2][2*c], a[3][2*c], a[2][2*c+1], a[3][2*c+1], b[2*c], b[2*c+1]);
        }
    }
}

__device__ __forceinline__ void mainloop16(__half* sm, const __half* Ag, int lda,
                                           const __half* Bg, int ldb, int T,
                                           float acc[2][8][4], int warpM, int warpN, int lane, int tid){
    load_tile16(sm, Ag, lda, tid);
    load_tile16(sm + A_HALFS, Bg, ldb, tid);
    cpcommit();
    load_tile16(sm + STAGE_H, Ag + 32, lda, tid);
    load_tile16(sm + STAGE_H + A_HALFS, Bg + 32, ldb, tid);
    cpcommit();
    for (int t = 0; t < T; t++){
        cpwait1();
        __syncthreads();
        const int u = t + 2;
        if (u < T){
            __half* Sd = sm + (u % NSTAGE) * STAGE_H;
            load_tile16(Sd, Ag + u*32, lda, tid);
            load_tile16(Sd + A_HALFS, Bg + u*32, ldb, tid);
        }
        cpcommit();
        const __half* Sa = sm + (t % NSTAGE) * STAGE_H;
        compute16(Sa, Sa + A_HALFS, acc, warpM, warpN, lane);
    }
}

#define ACC_INIT() float acc[2][8][4]; \
    _Pragma("unroll") for (int i=0;i<2;i++) \
    _Pragma("unroll") for (int j=0;j<8;j++) \
    _Pragma("unroll") for (int c=0;c<4;c++) acc[i][j][c]=0.f;

extern __shared__ __half smemh[];

// ---------- NT GEMM, fp16 out (+bias) ----------
__global__ __launch_bounds__(256, 2) void h16_gemm_f16out(
    const __half* __restrict__ A, const __half* __restrict__ B,
    __half* __restrict__ C, const float* __restrict__ bias, int M, int N, int K)
{
    const int tid = threadIdx.x, lane = tid & 31, warp = tid >> 5;
    const int warpM = warp & 3, warpN = warp >> 2;
    const int bm = blockIdx.y, bn = blockIdx.x;
    ACC_INIT();
    mainloop16(smemh, A + (size_t)bm*128*K, K, B + (size_t)bn*128*K, K, K/32,
               acc, warpM, warpN, lane, tid);
    const int gi = lane >> 2, tg = lane & 3;
    #pragma unroll
    for (int i = 0; i < 2; i++){
        const int row = bm*128 + warpM*32 + i*16 + gi;
        #pragma unroll
        for (int j = 0; j < 8; j++){
            const int col = bn*128 + warpN*64 + j*8 + tg*2;
            float v0 = acc[i][j][0], v1 = acc[i][j][1];
            float w0 = acc[i][j][2], w1 = acc[i][j][3];
            if (bias){
                const float b0 = bias[col], b1 = bias[col+1];
                v0 += b0; v1 += b1; w0 += b0; w1 += b1;
            }
            *(half2*)&C[(size_t)row * N + col]     = __floats2half2_rn(v0, v1);
            *(half2*)&C[(size_t)(row+8) * N + col] = __floats2half2_rn(w0, w1);
        }
    }
}

// ---------- NT GEMM, fp32 out (+add) ----------
__global__ __launch_bounds__(256, 2) void h16_gemm_f32out(
    const __half* __restrict__ A, const __half* __restrict__ B,
    float* __restrict__ C, const float* __restrict__ add, int M, int N, int K)
{
    const int tid = threadIdx.x, lane = tid & 31, warp = tid >> 5;
    const int warpM = warp & 3, warpN = warp >> 2;
    const int bm = blockIdx.y, bn = blockIdx.x;
    ACC_INIT();
    mainloop16(smemh, A + (size_t)bm*128*K, K, B + (size_t)bn*128*K, K, K/32,
               acc, warpM, warpN, lane, tid);
    const int gi = lane >> 2, tg = lane & 3;
    #pragma unroll
    for (int i = 0; i < 2; i++){
        const int row = bm*128 + warpM*32 + i*16 + gi;
        #pragma unroll
        for (int j = 0; j < 8; j++){
            const int col = bn*128 + warpN*64 + j*8 + tg*2;
            float2 v0 = make_float2(acc[i][j][0], acc[i][j][1]);
            float2 v1 = make_float2(acc[i][j][2], acc[i][j][3]);
            float2 r0 = *(const float2*)&add[(size_t)row * N + col];
            float2 r1 = *(const float2*)&add[(size_t)(row+8) * N + col];
            v0.x += r0.x; v0.y += r0.y; v1.x += r1.x; v1.y += r1.y;
            *(float2*)&C[(size_t)row * N + col]     = v0;
            *(float2*)&C[(size_t)(row+8) * N + col] = v1;
        }
    }
}

// ---------- fused two-expert down proj: C = add + A1*B1^T + A2*B2^T ----------
__global__ __launch_bounds__(256, 2) void h16_gemm_down2(
    const __half* __restrict__ A1, const __half* __restrict__ B1,
    const __half* __restrict__ A2, const __half* __restrict__ B2,
    float* __restrict__ C, const float* __restrict__ add, int M, int N, int K)
{
    const int tid = threadIdx.x, lane = tid & 31, warp = tid >> 5;
    const int warpM = warp & 3, warpN = warp >> 2;
    const int bm = blockIdx.y, bn = blockIdx.x;
    ACC_INIT();
    mainloop16(smemh, A1 + (size_t)bm*128*K, K, B1 + (size_t)bn*128*K, K, K/32,
               acc, warpM, warpN, lane, tid);
    __syncthreads();   // all warps done with smem before reuse
    mainloop16(smemh, A2 + (size_t)bm*128*K, K, B2 + (size_t)bn*128*K, K, K/32,
               acc, warpM, warpN, lane, tid);
    const int gi = lane >> 2, tg = lane & 3;
    #pragma unroll
    for (int i = 0; i < 2; i++){
        const int row = bm*128 + warpM*32 + i*16 + gi;
        #pragma unroll
        for (int j = 0; j < 8; j++){
            const int col = bn*128 + warpN*64 + j*8 + tg*2;
            float2 v0 = make_float2(acc[i][j][0], acc[i][j][1]);
            float2 v1 = make_float2(acc[i][j][2], acc[i][j][3]);
            float2 r0 = *(const float2*)&add[(size_t)row * N + col];
            float2 r1 = *(const float2*)&add[(size_t)(row+8) * N + col];
            v0.x += r0.x; v0.y += r0.y; v1.x += r1.x; v1.y += r1.y;
            *(float2*)&C[(size_t)row * N + col]     = v0;
            *(float2*)&C[(size_t)(row+8) * N + col] = v1;
        }
    }
}

// ---------- attention scores: fp16 logits, causal (masked blocks skipped) ----------
__global__ __launch_bounds__(256, 2) void h16_scores(
    const __half* __restrict__ Q, const __half* __restrict__ Km, __half* __restrict__ Ph)
{
    const int bm = blockIdx.y, bn = blockIdx.x;
    if (bn > bm) return;   // never read downstream
    const int z = blockIdx.z, b = z >> 4, h = z & 15;
    const int tid = threadIdx.x, lane = tid & 31, warp = tid >> 5;
    const int warpM = warp & 3, warpN = warp >> 2;
    __half* Cb = Ph + (size_t)z * Sz * Sz;
    const __half* Ag = Q  + (size_t)(b*Sz + bm*128) * Dz + (size_t)h * DHz;
    const __half* Bg = Km + (size_t)(b*Sz + bn*128) * Dz + (size_t)h * DHz;
    ACC_INIT();
    mainloop16(smemh, Ag, Dz, Bg, Dz, DHz/32, acc, warpM, warpN, lane, tid);
    const int gi = lane >> 2, tg = lane & 3;
    #pragma unroll
    for (int i = 0; i < 2; i++){
        const int row0 = bm*128 + warpM*32 + i*16 + gi;
        #pragma unroll
        for (int j = 0; j < 8; j++){
            const int col = bn*128 + warpN*64 + j*8 + tg*2;
            float v0 = (col   <= row0  ) ? acc[i][j][0]*ATTN_SCALE : MASK_NEG;
            float v1 = (col+1 <= row0  ) ? acc[i][j][1]*ATTN_SCALE : MASK_NEG;
            float w0 = (col   <= row0+8) ? acc[i][j][2]*ATTN_SCALE : MASK_NEG;
            float w1 = (col+1 <= row0+8) ? acc[i][j][3]*ATTN_SCALE : MASK_NEG;
            *(half2*)&Cb[(size_t)row0 * Sz + col]     = __floats2half2_rn(v0, v1);
            *(half2*)&Cb[(size_t)(row0+8) * Sz + col] = __floats2half2_rn(w0, w1);
        }
    }
}

// ---------- attention ctx: Cx = P Vt^T, causal K-trim, normalized, fp16 out ----------
__global__ __launch_bounds__(256, 2) void h16_ctx(
    const __half* __restrict__ P, const __half* __restrict__ Vt,
    const float* __restrict__ rowsum, __half* __restrict__ Cx)
{
    const int z = blockIdx.z, b = z >> 4, h = z & 15;
    const int bm = blockIdx.y;
    const int tid = threadIdx.x, lane = tid & 31, warp = tid >> 5;
    const int warpM = warp & 3, warpN = warp >> 2;
    const __half* Ag = P  + (size_t)z * Sz * Sz + (size_t)bm * 128 * Sz;
    const __half* Bg = Vt + (size_t)z * 128 * Sz;
    ACC_INIT();
    mainloop16(smemh, Ag, Sz, Bg, Sz, (bm + 1) * 4, acc, warpM, warpN, lane, tid);
    const int gi = lane >> 2, tg = lane & 3;
    #pragma unroll
    for (int i = 0; i < 2; i++){
        const int rloc = bm*128 + warpM*32 + i*16 + gi;
        const float inv0 = 1.f / rowsum[(size_t)z * Sz + rloc];
        const float inv1 = 1.f / rowsum[(size_t)z * Sz + rloc + 8];
        const size_t row0 = (size_t)(b*Sz) + rloc;
        #pragma unroll
        for (int j = 0; j < 8; j++){
            const int col = h*DHz + warpN*64 + j*8 + tg*2;
            *(half2*)&Cx[row0 * Dz + col]     = __floats2half2_rn(acc[i][j][0]*inv0, acc[i][j][1]*inv0);
            *(half2*)&Cx[(row0+8) * Dz + col] = __floats2half2_rn(acc[i][j][2]*inv1, acc[i][j][3]*inv1);
        }
    }
}

// ================= helpers / elementwise =================
// consolidated rounding: grid.y picks one of up to 6 equal-sized weights
__global__ __launch_bounds__(256) void h16_round_multi(
    const float* s0, const float* s1, const float* s2, const float* s3,
    const float* s4, const float* s5, __half* dst, int per8)
{
    const int i = blockIdx.x * 256 + threadIdx.x;
    if (i >= per8) return;
    const int w = blockIdx.y;
    const float* src = (w==0)?s0:(w==1)?s1:(w==2)?s2:(w==3)?s3:(w==4)?s4:s5;
    __half* d = dst + (size_t)w * per8 * 8;
    float4 v0 = ((const float4*)src)[2*(size_t)i];
    float4 v1 = ((const float4*)src)[2*(size_t)i + 1];
    half2 h0 = __floats2half2_rn(v0.x, v0.y), h1 = __floats2half2_rn(v0.z, v0.w);
    half2 h2 = __floats2half2_rn(v1.x, v1.y), h3 = __floats2half2_rn(v1.z, v1.w);
    uint4 u;
    u.x = *(unsigned*)&h0; u.y = *(unsigned*)&h1;
    u.z = *(unsigned*)&h2; u.w = *(unsigned*)&h3;
    ((uint4*)d)[i] = u;
}

// transpose vh[token][Dz] -> vt[(b*16+h)*128+dh][token_in_batch]
__global__ __launch_bounds__(256) void transpose_v16(const __half* __restrict__ v, __half* __restrict__ vt)
{
    __shared__ unsigned short tile[32][33];
    const int tid = threadIdx.x;
    const int d0 = blockIdx.x * 32, t0 = blockIdx.y * 32;
    const int tx = tid & 31, ty = tid >> 5;
    #pragma unroll
    for (int it = 0; it < 4; it++){
        const int tok = t0 + ty + it*8;
        tile[ty + it*8][tx] = *(const unsigned short*)&v[(size_t)tok * Dz + d0 + tx];
    }
    __syncthreads();
    #pragma unroll
    for (int it = 0; it < 4; it++){
        const int dh_loc = ty + it*8;
        const int gd = d0 + dh_loc;
        const int tok = t0 + tx;
        const int bb = tok >> 11, tin = tok & 2047;
        *(unsigned short*)&vt[((size_t)(bb*16) * 128 + gd) * Sz + tin] = tile[tx][dh_loc];
    }
}

__global__ __launch_bounds__(256) void rmsnorm_kernel(
    const float* __restrict__ x, const float* __restrict__ w,
    __half* __restrict__ out, float* __restrict__ out_raw)
{
    const int row = blockIdx.x;
    const float* xr = x + (size_t)row * Dz;
    __half* orow = out + (size_t)row * Dz;
    const int tid = threadIdx.x;
    float ss = 0.f;
    #pragma unroll
    for (int i = tid*4; i < Dz; i += 1024) {
        float4 v = *(const float4*)(xr + i);
        ss += v.x*v.x + v.y*v.y + v.z*v.z + v.w*v.w;
    }
    __shared__ float red[256];
    red[tid] = ss; __syncthreads();
    for (int s = 128; s > 0; s >>= 1) { if (tid < s) red[tid] += red[tid+s]; __syncthreads(); }
    const float scale = rsqrtf(red[0] / (float)Dz + 1e-6f);
    #pragma unroll
    for (int i = tid*4; i < Dz; i += 1024) {
        float4 v = *(const float4*)(xr + i);
        float4 ww = *(const float4*)(w + i);
        float4 o;
        o.x = v.x*scale*ww.x; o.y = v.y*scale*ww.y;
        o.z = v.z*scale*ww.z; o.w = v.w*scale*ww.w;
        if (out_raw) *(float4*)(out_raw + (size_t)row * Dz + i) = o;
        *(half2*)(orow + i)     = __floats2half2_rn(o.x, o.y);
        *(half2*)(orow + i + 2) = __floats2half2_rn(o.z, o.w);
    }
}

__global__ __launch_bounds__(256) void rope_kernel16(__half* __restrict__ q, __half* __restrict__ k)
{
    const size_t idx = (size_t)blockIdx.x * 256 + threadIdx.x;
    if (idx >= (size_t)NTz * Hz * 64) return;
    const int    j    = (int)(idx & 63);
    const size_t th   = idx >> 6;
    const int    head = (int)(th & 15);
    const size_t tok  = th >> 4;
    const int    s    = (int)(tok & (Sz - 1));
    const double inv  = exp(-(double)(2*j) / 128.0 * 9.210340371976184);
    const double ang  = (double)s * inv;
    const float  c  = (float)cos(ang);
    const float  sn = (float)sin(ang);
    const size_t base = tok * (size_t)Dz + (size_t)head * DHz + j;
    float q1 = __half2float(q[base]), q2 = __half2float(q[base + 64]);
    q[base]      = __float2half_rn(q1*c - q2*sn);
    q[base + 64] = __float2half_rn(q2*c + q1*sn);
    float k1 = __half2float(k[base]), k2 = __half2float(k[base + 64]);
    k[base]      = __float2half_rn(k1*c - k2*sn);
    k[base + 64] = __float2half_rn(k2*c + k1*sn);
}

// causal softmax, IN-PLACE on fp16 logits -> fp16 probs + fp32 rowsum
__global__ __launch_bounds__(256) void softmax_kernel16(__half* __restrict__ Ph, float* __restrict__ rowsum)
{
    const size_t row = blockIdx.x;
    const int sloc = (int)(row & (Sz - 1));
    const int len = ((sloc >> 7) + 1) << 7;
    __half* p = Ph + row * (size_t)Sz;
    const int tid = threadIdx.x;
    float m = -1e30f;
    for (int i = tid*8; i < len; i += 2048) {
        uint4 u = *(const uint4*)(p + i);
        const half2* hp = (const half2*)&u;
        #pragma unroll
        for (int q = 0; q < 4; q++){
            float2 f = __half22float2(hp[q]);
            m = fmaxf(m, fmaxf(f.x, f.y));
        }
    }
    __shared__ float red[256];
    red[tid] = m; __syncthreads();
    for (int s = 128; s > 0; s >>= 1) { if (tid < s) red[tid] = fmaxf(red[tid], red[tid+s]); __syncthreads(); }
    m = red[0];
    __syncthreads();
    float sum = 0.f;
    for (int i = tid*8; i < len; i += 2048) {
        uint4 u = *(const uint4*)(p + i);
        half2* hp = (half2*)&u;
        #pragma unroll
        for (int q = 0; q < 4; q++){
            float2 f = __half22float2(hp[q]);
            half2 e = __floats2half2_rn(expf(f.x - m), expf(f.y - m));
            float2 ef = __half22float2(e);
            sum += ef.x + ef.y;
            hp[q] = e;
        }
        *(uint4*)(p + i) = u;
    }
    red[tid] = sum; __syncthreads();
    for (int s = 128; s > 0; s >>= 1) { if (tid < s) red[tid] += red[tid+s]; __syncthreads(); }
    if (tid == 0) rowsum[row] = red[0];
}

__global__ __launch_bounds__(256) void router_kernel(
    const float* __restrict__ h, const float* __restrict__ rw,
    const float* __restrict__ rb, int* __restrict__ choice)
{
    const int t = blockIdx.x;
    const float* xr = h + (size_t)t * Dz;
    const int tid = threadIdx.x;
    float s0 = 0.f, s1 = 0.f;
    #pragma unroll
    for (int i = tid*4; i < Dz; i += 1024) {
        float4 v  = *(const float4*)(xr + i);
        float4 w0 = *(const float4*)(rw + i);
        float4 w1 = *(const float4*)(rw + Dz + i);
        s0 += v.x*w0.x + v.y*w0.y + v.z*w0.z + v.w*w0.w;
        s1 += v.x*w1.x + v.y*w1.y + v.z*w1.z + v.w*w1.w;
    }
    __shared__ float r0[256], r1[256];
    r0[tid] = s0; r1[tid] = s1; __syncthreads();
    for (int s = 128; s > 0; s >>= 1) {
        if (tid < s) { r0[tid] += r0[tid+s]; r1[tid] += r1[tid+s]; }
        __syncthreads();
    }
    if (tid == 0) {
        const float l0 = r0[0] + rb[0], l1 = r1[0] + rb[1];
        choice[t] = (l1 > l0) ? 1 : 0;
    }
}

__global__ __launch_bounds__(256) void act_kernel16(
    __half* __restrict__ gate, const __half* __restrict__ up,
    const int* __restrict__ choice, int e)
{
    const int f = blockIdx.x * 256 + threadIdx.x;
    if (f >= Fz) return;
    const int tok = blockIdx.y;
    const size_t idx = (size_t)tok * Fz + f;
    if (choice[tok] == e) {
        const float g = __half2float(gate[idx]);
        const float u = __half2float(up[idx]);
        gate[idx] = __float2half_rn((g / (1.f + expf(-g))) * u);
    } else {
        gate[idx] = __float2half_rn(0.f);
    }
}

// ================= launch =================
extern "C" void kernel_launch(void* const* d_in, const int* in_sizes, int n_in,
                              void* d_out, int out_size)
{
    const float* x    = (const float*)d_in[0];
    const float* ln1w = (const float*)d_in[1];
    const float* wq   = (const float*)d_in[2];
    const float* bq   = (const float*)d_in[3];
    const float* wk   = (const float*)d_in[4];
    const float* bk   = (const float*)d_in[5];
    const float* wv   = (const float*)d_in[6];
    const float* bv   = (const float*)d_in[7];
    const float* wo   = (const float*)d_in[8];
    const float* ln2w = (const float*)d_in[9];
    const float* e1g  = (const float*)d_in[10];
    const float* e1u  = (const float*)d_in[11];
    const float* e1d  = (const float*)d_in[12];
    const float* e2g  = (const float*)d_in[13];
    const float* e2u  = (const float*)d_in[14];
    const float* e2d  = (const float*)d_in[15];
    const float* rw   = (const float*)d_in[16];
    const float* rb   = (const float*)d_in[17];
    float* out = (float*)d_out;

    __half *h1h, *qh, *kh, *vh, *ctxh, *ph, *gateh, *gate2h, *uph, *wrh;
    float *h2, *h3raw, *rs;
    int* choice;
    cudaGetSymbolAddress((void**)&h1h,   g_h1h);
    cudaGetSymbolAddress((void**)&qh,    g_qh);
    cudaGetSymbolAddress((void**)&kh,    g_kh);
    cudaGetSymbolAddress((void**)&vh,    g_vh);
    cudaGetSymbolAddress((void**)&ctxh,  g_ctxh);
    cudaGetSymbolAddress((void**)&h2,    g_h2);
    cudaGetSymbolAddress((void**)&h3raw, g_h3raw);
    cudaGetSymbolAddress((void**)&ph,    g_ph);
    cudaGetSymbolAddress((void**)&rs,    g_rs);
    cudaGetSymbolAddress((void**)&gateh,  g_gateh);
    cudaGetSymbolAddress((void**)&gate2h, g_gate2h);
    cudaGetSymbolAddress((void**)&uph,    g_uph);
    cudaGetSymbolAddress((void**)&wrh,    g_wrh);
    cudaGetSymbolAddress((void**)&choice, g_choice);

    cudaFuncSetAttribute(h16_gemm_f16out, cudaFuncAttributeMaxDynamicSharedMemorySize, SMEM_BYTES);
    cudaFuncSetAttribute(h16_gemm_f32out, cudaFuncAttributeMaxDynamicSharedMemorySize, SMEM_BYTES);
    cudaFuncSetAttribute(h16_gemm_down2,  cudaFuncAttributeMaxDynamicSharedMemorySize, SMEM_BYTES);
    cudaFuncSetAttribute(h16_scores,      cudaFuncAttributeMaxDynamicSharedMemorySize, SMEM_BYTES);
    cudaFuncSetAttribute(h16_ctx,         cudaFuncAttributeMaxDynamicSharedMemorySize, SMEM_BYTES);

    // --- weight pre-rounding: 2 consolidated launches ---
    {   // attention weights: 4 x (Dz*Dz)
        const int per8 = (Dz*Dz)/8;                       // 524288
        h16_round_multi<<<dim3(per8/256, 4), 256>>>(wq, wk, wv, wo, wo, wo, wrh + WR_Q, per8);
    }
    {   // MoE weights: 6 x (Fz*Dz)
        const int per8 = (Fz*Dz)/8;                       // 1409024
        h16_round_multi<<<dim3(per8/256, 6), 256>>>(e1g, e1u, e1d, e2g, e2u, e2d, wrh + WR_E1G, per8);
    }

    // --- attention block ---  (V GEMM is launch #6 -> ncu -s 5 -c 1 captures it)
    rmsnorm_kernel<<<NTz, 256>>>(x, ln1w, h1h, nullptr);
    h16_gemm_f16out<<<dim3(Dz/128, NTz/128), 256, SMEM_BYTES>>>(h1h, wrh+WR_Q, qh, bq, NTz, Dz, Dz);
    h16_gemm_f16out<<<dim3(Dz/128, NTz/128), 256, SMEM_BYTES>>>(h1h, wrh+WR_K, kh, bk, NTz, Dz, Dz);
    h16_gemm_f16out<<<dim3(Dz/128, NTz/128), 256, SMEM_BYTES>>>(h1h, wrh+WR_V, vh, bv, NTz, Dz, Dz);
    rope_kernel16<<<(NTz*Hz*64)/256, 256>>>(qh, kh);
    h16_scores<<<dim3(Sz/128, Sz/128, BHz), 256, SMEM_BYTES>>>(qh, kh, ph);
    __half* vt = kh;   // kh's memory reused as transposed V after scores consumed it
    transpose_v16<<<dim3(Dz/32, NTz/32), 256>>>(vh, vt);
    softmax_kernel16<<<BHz*Sz, 256>>>(ph, rs);
    h16_ctx<<<dim3(1, Sz/128, BHz), 256, SMEM_BYTES>>>(ph, vt, rs, ctxh);
    h16_gemm_f32out<<<dim3(Dz/128, NTz/128), 256, SMEM_BYTES>>>(ctxh, wrh+WR_O, h2, x, NTz, Dz, Dz);

    // --- MoE block ---
    rmsnorm_kernel<<<NTz, 256>>>(h2, ln2w, h1h, h3raw);
    router_kernel<<<NTz, 256>>>(h3raw, rw, rb, choice);

    h16_gemm_f16out<<<dim3(Fz/128, NTz/128), 256, SMEM_BYTES>>>(h1h, wrh+WR_E1G, gateh,  nullptr, NTz, Fz, Dz);
    h16_gemm_f16out<<<dim3(Fz/128, NTz/128), 256, SMEM_BYTES>>>(h1h, wrh+WR_E1U, uph,    nullptr, NTz, Fz, Dz);
    act_kernel16<<<dim3((Fz+255)/256, NTz), 256>>>(gateh, uph, choice, 0);
    h16_gemm_f16out<<<dim3(Fz/128, NTz/128), 256, SMEM_BYTES>>>(h1h, wrh+WR_E2G, gate2h, nullptr, NTz, Fz, Dz);
    h16_gemm_f16out<<<dim3(Fz/128, NTz/128), 256, SMEM_BYTES>>>(h1h, wrh+WR_E2U, uph,    nullptr, NTz, Fz, Dz);
    act_kernel16<<<dim3((Fz+255)/256, NTz), 256>>>(gate2h, uph, choice, 1);
    h16_gemm_down2<<<dim3(Dz/128, NTz/128), 256, SMEM_BYTES>>>(gateh, wrh+WR_E1D, gate2h, wrh+WR_E2D,
                                                               out, h2, NTz, Dz, Fz);
}

// round 17
// speedup vs baseline: 1.1136x; 1.1136x over previous
#include <cuda_runtime.h>
#include <cuda_fp16.h>
#include <math.h>
#include <stdint.h>

#define Bz   2
#define Sz   2048
#define Dz   2048
#define Hz   16
#define DHz  128
#define Fz   5504
#define NTz  (Bz*Sz)      // 4096 tokens
#define BHz  (Bz*Hz)      // 32
#define ATTN_SCALE 0.08838834764831845f   // 1/sqrt(128)
#define MASK_NEG  (-60000.0f)             // fp16-representable "-inf"

// ---------------- scratch (device globals; allocation-free) ----------------
__device__ __half g_h1h [(size_t)NTz*Dz];     // rmsnorm out (fp16)
__device__ __half g_qh  [(size_t)NTz*Dz];
__device__ __half g_kh  [(size_t)NTz*Dz];     // k; later vt (transposed V)
__device__ __half g_vh  [(size_t)NTz*Dz];
__device__ __half g_ctxh[(size_t)NTz*Dz];
__device__ float  g_h2  [(size_t)NTz*Dz];     // attn residual (fp32)
__device__ float  g_h3raw[(size_t)NTz*Dz];    // fp32 rmsnorm2 out for router
__device__ __half g_ph  [(size_t)BHz*Sz*Sz];  // fp16 logits -> probs (in-place)
__device__ float  g_rs  [(size_t)BHz*Sz];
__device__ __half g_gateh [(size_t)NTz*Fz];   // expert1 act
__device__ __half g_gate2h[(size_t)NTz*Fz];   // expert2 act
__device__ __half g_uph   [(size_t)NTz*Fz];
__device__ int    g_choice[NTz];
// pre-rounded fp16 weights
#define WR_Q   0
#define WR_K   4194304
#define WR_V   8388608
#define WR_O   12582912
#define WR_E1G 16777216
#define WR_E1U 28049408
#define WR_E1D 39321600
#define WR_E2G 50593792
#define WR_E2U 61865984
#define WR_E2D 73138176
#define WR_TOT 84410368
__device__ __half g_wrh[(size_t)WR_TOT];

// ================= FP16 MMA machinery (v3: pitch 32, K=64 superstages) =================
// Block tile 128x128, 256 threads, warp tile 32(M)x64(N).
// PITCH_H = 32 halfs (64 B/row): fragment LDS.128 address = lane*16 bytes
// (fully contiguous per warp -> conflict-free AND 16B-aligned).
// Superstage = K=64 = 4 tiles [A0|B0|A1|B1]; double-buffered; one
// wait_group 0 + one __syncthreads per superstage.

#define PITCH_H 32
#define TILE_HALFS (128*PITCH_H)       // 4096 halfs = 8192 B
#define SUPER_HALFS (4*TILE_HALFS)     // 16384 halfs = 32768 B
#define SMEM_BYTES (2*SUPER_HALFS*2)   // 65536 B

__device__ __forceinline__ unsigned sptr(const void* p){ return (unsigned)__cvta_generic_to_shared(p); }
__device__ __forceinline__ void cpa16(unsigned s, const void* g){
    asm volatile("cp.async.cg.shared.global [%0], [%1], 16;\n" :: "r"(s), "l"(g));
}
__device__ __forceinline__ void cpcommit(){ asm volatile("cp.async.commit_group;\n" ::); }
__device__ __forceinline__ void cpwait0(){ asm volatile("cp.async.wait_group 0;\n" ::); }
__device__ __forceinline__ void mma16816(float* c, unsigned a0,unsigned a1,unsigned a2,unsigned a3,
                                         unsigned b0, unsigned b1){
    asm volatile("mma.sync.aligned.m16n8k16.row.col.f32.f16.f16.f32 "
                 "{%0,%1,%2,%3},{%4,%5,%6,%7},{%8,%9},{%0,%1,%2,%3};\n"
                 : "+f"(c[0]),"+f"(c[1]),"+f"(c[2]),"+f"(c[3])
                 : "r"(a0),"r"(a1),"r"(a2),"r"(a3),"r"(b0),"r"(b1));
}

// load 128 rows x 32 k-halfs into smem [row][k] pitch 32 (dense 64B rows)
__device__ __forceinline__ void load_tile16(__half* S, const __half* G, int ld, int tid){
    const int r = tid >> 1, cb = (tid & 1) * 16;
    const __half* g = G + (size_t)r * ld + cb;
    unsigned s = sptr(S) + (unsigned)(r * PITCH_H + cb) * 2u;
    cpa16(s, g);
    cpa16(s + 16u, g + 8);
}

// one K=64 superstage: [A0|B0|A1|B1]
__device__ __forceinline__ void load_super(__half* base, const __half* Ag, int lda,
                                           const __half* Bg, int ldb, int koff, int tid){
    load_tile16(base,                Ag + koff,      lda, tid);
    load_tile16(base +   TILE_HALFS, Bg + koff,      ldb, tid);
    load_tile16(base + 2*TILE_HALFS, Ag + koff + 32, lda, tid);
    load_tile16(base + 3*TILE_HALFS, Bg + koff + 32, ldb, tid);
}

// Virtual-K bijection (identical on A and B -> exact): one 32-k sub-tile.
__device__ __forceinline__ void compute16(const __half* __restrict__ As, const __half* __restrict__ Bs,
                                          float acc[2][8][4], int warpM, int warpN, int lane){
    const int gi = lane >> 2, tg = lane & 3;
    const int r0 = warpM*32 + gi;
    unsigned a[4][4];
    #pragma unroll
    for (int r = 0; r < 4; r++)
        *(uint4*)a[r] = *(const uint4*)(As + (r0 + r*8)*PITCH_H + tg*8);
    #pragma unroll
    for (int j = 0; j < 8; j++){
        unsigned b[4];
        *(uint4*)b = *(const uint4*)(Bs + (warpN*64 + j*8 + gi)*PITCH_H + tg*8);
        #pragma unroll
        for (int c = 0; c < 2; c++){
            mma16816(acc[0][j], a[0][2*c], a[1][2*c], a[0][2*c+1], a[1][2*c+1], b[2*c], b[2*c+1]);
            mma16816(acc[1][j], a[2][2*c], a[3][2*c], a[2][2*c+1], a[3][2*c+1], b[2*c], b[2*c+1]);
        }
    }
}

// double-buffered superstage mainloop. T32 = number of 32-k tiles (even).
__device__ __forceinline__ void mainloop16(__half* sm, const __half* Ag, int lda,
                                           const __half* Bg, int ldb, int T32,
                                           float acc[2][8][4], int warpM, int warpN, int lane, int tid){
    const int TS = T32 >> 1;
    load_super(sm, Ag, lda, Bg, ldb, 0, tid);
    cpcommit();
    for (int t = 0; t < TS; t++){
        cpwait0();
        __syncthreads();
        if (t + 1 < TS){
            load_super(sm + ((t+1) & 1) * SUPER_HALFS, Ag, lda, Bg, ldb, (t+1)*64, tid);
            cpcommit();
        }
        const __half* base = sm + (t & 1) * SUPER_HALFS;
        compute16(base,                base +   TILE_HALFS, acc, warpM, warpN, lane);
        compute16(base + 2*TILE_HALFS, base + 3*TILE_HALFS, acc, warpM, warpN, lane);
    }
    __syncthreads();   // protect smem for callers that run a second mainloop
}

#define ACC_INIT() float acc[2][8][4]; \
    _Pragma("unroll") for (int i=0;i<2;i++) \
    _Pragma("unroll") for (int j=0;j<8;j++) \
    _Pragma("unroll") for (int c=0;c<4;c++) acc[i][j][c]=0.f;

extern __shared__ __half smemh[];

// ---------- NT GEMM, fp16 out (+bias) ----------
__global__ __launch_bounds__(256, 2) void h16_gemm_f16out(
    const __half* __restrict__ A, const __half* __restrict__ B,
    __half* __restrict__ C, const float* __restrict__ bias, int M, int N, int K)
{
    const int tid = threadIdx.x, lane = tid & 31, warp = tid >> 5;
    const int warpM = warp & 3, warpN = warp >> 2;
    const int bm = blockIdx.y, bn = blockIdx.x;
    ACC_INIT();
    mainloop16(smemh, A + (size_t)bm*128*K, K, B + (size_t)bn*128*K, K, K/32,
               acc, warpM, warpN, lane, tid);
    const int gi = lane >> 2, tg = lane & 3;
    #pragma unroll
    for (int i = 0; i < 2; i++){
        const int row = bm*128 + warpM*32 + i*16 + gi;
        #pragma unroll
        for (int j = 0; j < 8; j++){
            const int col = bn*128 + warpN*64 + j*8 + tg*2;
            float v0 = acc[i][j][0], v1 = acc[i][j][1];
            float w0 = acc[i][j][2], w1 = acc[i][j][3];
            if (bias){
                const float b0 = bias[col], b1 = bias[col+1];
                v0 += b0; v1 += b1; w0 += b0; w1 += b1;
            }
            *(half2*)&C[(size_t)row * N + col]     = __floats2half2_rn(v0, v1);
            *(half2*)&C[(size_t)(row+8) * N + col] = __floats2half2_rn(w0, w1);
        }
    }
}

// ---------- NT GEMM, fp32 out (+add) ----------
__global__ __launch_bounds__(256, 2) void h16_gemm_f32out(
    const __half* __restrict__ A, const __half* __restrict__ B,
    float* __restrict__ C, const float* __restrict__ add, int M, int N, int K)
{
    const int tid = threadIdx.x, lane = tid & 31, warp = tid >> 5;
    const int warpM = warp & 3, warpN = warp >> 2;
    const int bm = blockIdx.y, bn = blockIdx.x;
    ACC_INIT();
    mainloop16(smemh, A + (size_t)bm*128*K, K, B + (size_t)bn*128*K, K, K/32,
               acc, warpM, warpN, lane, tid);
    const int gi = lane >> 2, tg = lane & 3;
    #pragma unroll
    for (int i = 0; i < 2; i++){
        const int row = bm*128 + warpM*32 + i*16 + gi;
        #pragma unroll
        for (int j = 0; j < 8; j++){
            const int col = bn*128 + warpN*64 + j*8 + tg*2;
            float2 v0 = make_float2(acc[i][j][0], acc[i][j][1]);
            float2 v1 = make_float2(acc[i][j][2], acc[i][j][3]);
            float2 r0 = *(const float2*)&add[(size_t)row * N + col];
            float2 r1 = *(const float2*)&add[(size_t)(row+8) * N + col];
            v0.x += r0.x; v0.y += r0.y; v1.x += r1.x; v1.y += r1.y;
            *(float2*)&C[(size_t)row * N + col]     = v0;
            *(float2*)&C[(size_t)(row+8) * N + col] = v1;
        }
    }
}

// ---------- fused two-expert down proj: C = add + A1*B1^T + A2*B2^T ----------
__global__ __launch_bounds__(256, 2) void h16_gemm_down2(
    const __half* __restrict__ A1, const __half* __restrict__ B1,
    const __half* __restrict__ A2, const __half* __restrict__ B2,
    float* __restrict__ C, const float* __restrict__ add, int M, int N, int K)
{
    const int tid = threadIdx.x, lane = tid & 31, warp = tid >> 5;
    const int warpM = warp & 3, warpN = warp >> 2;
    const int bm = blockIdx.y, bn = blockIdx.x;
    ACC_INIT();
    mainloop16(smemh, A1 + (size_t)bm*128*K, K, B1 + (size_t)bn*128*K, K, K/32,
               acc, warpM, warpN, lane, tid);
    mainloop16(smemh, A2 + (size_t)bm*128*K, K, B2 + (size_t)bn*128*K, K, K/32,
               acc, warpM, warpN, lane, tid);
    const int gi = lane >> 2, tg = lane & 3;
    #pragma unroll
    for (int i = 0; i < 2; i++){
        const int row = bm*128 + warpM*32 + i*16 + gi;
        #pragma unroll
        for (int j = 0; j < 8; j++){
            const int col = bn*128 + warpN*64 + j*8 + tg*2;
            float2 v0 = make_float2(acc[i][j][0], acc[i][j][1]);
            float2 v1 = make_float2(acc[i][j][2], acc[i][j][3]);
            float2 r0 = *(const float2*)&add[(size_t)row * N + col];
            float2 r1 = *(const float2*)&add[(size_t)(row+8) * N + col];
            v0.x += r0.x; v0.y += r0.y; v1.x += r1.x; v1.y += r1.y;
            *(float2*)&C[(size_t)row * N + col]     = v0;
            *(float2*)&C[(size_t)(row+8) * N + col] = v1;
        }
    }
}

// ---------- attention scores: fp16 logits, causal (masked blocks skipped) ----------
__global__ __launch_bounds__(256, 2) void h16_scores(
    const __half* __restrict__ Q, const __half* __restrict__ Km, __half* __restrict__ Ph)
{
    const int bm = blockIdx.y, bn = blockIdx.x;
    if (bn > bm) return;   // never read downstream
    const int z = blockIdx.z, b = z >> 4, h = z & 15;
    const int tid = threadIdx.x, lane = tid & 31, warp = tid >> 5;
    const int warpM = warp & 3, warpN = warp >> 2;
    __half* Cb = Ph + (size_t)z * Sz * Sz;
    const __half* Ag = Q  + (size_t)(b*Sz + bm*128) * Dz + (size_t)h * DHz;
    const __half* Bg = Km + (size_t)(b*Sz + bn*128) * Dz + (size_t)h * DHz;
    ACC_INIT();
    mainloop16(smemh, Ag, Dz, Bg, Dz, DHz/32, acc, warpM, warpN, lane, tid);
    const int gi = lane >> 2, tg = lane & 3;
    #pragma unroll
    for (int i = 0; i < 2; i++){
        const int row0 = bm*128 + warpM*32 + i*16 + gi;
        #pragma unroll
        for (int j = 0; j < 8; j++){
            const int col = bn*128 + warpN*64 + j*8 + tg*2;
            float v0 = (col   <= row0  ) ? acc[i][j][0]*ATTN_SCALE : MASK_NEG;
            float v1 = (col+1 <= row0  ) ? acc[i][j][1]*ATTN_SCALE : MASK_NEG;
            float w0 = (col   <= row0+8) ? acc[i][j][2]*ATTN_SCALE : MASK_NEG;
            float w1 = (col+1 <= row0+8) ? acc[i][j][3]*ATTN_SCALE : MASK_NEG;
            *(half2*)&Cb[(size_t)row0 * Sz + col]     = __floats2half2_rn(v0, v1);
            *(half2*)&Cb[(size_t)(row0+8) * Sz + col] = __floats2half2_rn(w0, w1);
        }
    }
}

// ---------- attention ctx: Cx = P Vt^T, causal K-trim, normalized, fp16 out ----------
__global__ __launch_bounds__(256, 2) void h16_ctx(
    const __half* __restrict__ P, const __half* __restrict__ Vt,
    const float* __restrict__ rowsum, __half* __restrict__ Cx)
{
    const int z = blockIdx.z, b = z >> 4, h = z & 15;
    const int bm = blockIdx.y;
    const int tid = threadIdx.x, lane = tid & 31, warp = tid >> 5;
    const int warpM = warp & 3, warpN = warp >> 2;
    const __half* Ag = P  + (size_t)z * Sz * Sz + (size_t)bm * 128 * Sz;
    const __half* Bg = Vt + (size_t)z * 128 * Sz;
    ACC_INIT();
    mainloop16(smemh, Ag, Sz, Bg, Sz, (bm + 1) * 4, acc, warpM, warpN, lane, tid);
    const int gi = lane >> 2, tg = lane & 3;
    #pragma unroll
    for (int i = 0; i < 2; i++){
        const int rloc = bm*128 + warpM*32 + i*16 + gi;
        const float inv0 = 1.f / rowsum[(size_t)z * Sz + rloc];
        const float inv1 = 1.f / rowsum[(size_t)z * Sz + rloc + 8];
        const size_t row0 = (size_t)(b*Sz) + rloc;
        #pragma unroll
        for (int j = 0; j < 8; j++){
            const int col = h*DHz + warpN*64 + j*8 + tg*2;
            *(half2*)&Cx[row0 * Dz + col]     = __floats2half2_rn(acc[i][j][0]*inv0, acc[i][j][1]*inv0);
            *(half2*)&Cx[(row0+8) * Dz + col] = __floats2half2_rn(acc[i][j][2]*inv1, acc[i][j][3]*inv1);
        }
    }
}

// ================= helpers / elementwise (unchanged) =================
__global__ __launch_bounds__(256) void h16_round_multi(
    const float* s0, const float* s1, const float* s2, const float* s3,
    const float* s4, const float* s5, __half* dst, int per8)
{
    const int i = blockIdx.x * 256 + threadIdx.x;
    if (i >= per8) return;
    const int w = blockIdx.y;
    const float* src = (w==0)?s0:(w==1)?s1:(w==2)?s2:(w==3)?s3:(w==4)?s4:s5;
    __half* d = dst + (size_t)w * per8 * 8;
    float4 v0 = ((const float4*)src)[2*(size_t)i];
    float4 v1 = ((const float4*)src)[2*(size_t)i + 1];
    half2 h0 = __floats2half2_rn(v0.x, v0.y), h1 = __floats2half2_rn(v0.z, v0.w);
    half2 h2 = __floats2half2_rn(v1.x, v1.y), h3 = __floats2half2_rn(v1.z, v1.w);
    uint4 u;
    u.x = *(unsigned*)&h0; u.y = *(unsigned*)&h1;
    u.z = *(unsigned*)&h2; u.w = *(unsigned*)&h3;
    ((uint4*)d)[i] = u;
}

__global__ __launch_bounds__(256) void transpose_v16(const __half* __restrict__ v, __half* __restrict__ vt)
{
    __shared__ unsigned short tile[32][33];
    const int tid = threadIdx.x;
    const int d0 = blockIdx.x * 32, t0 = blockIdx.y * 32;
    const int tx = tid & 31, ty = tid >> 5;
    #pragma unroll
    for (int it = 0; it < 4; it++){
        const int tok = t0 + ty + it*8;
        tile[ty + it*8][tx] = *(const unsigned short*)&v[(size_t)tok * Dz + d0 + tx];
    }
    __syncthreads();
    #pragma unroll
    for (int it = 0; it < 4; it++){
        const int dh_loc = ty + it*8;
        const int gd = d0 + dh_loc;
        const int tok = t0 + tx;
        const int bb = tok >> 11, tin = tok & 2047;
        *(unsigned short*)&vt[((size_t)(bb*16) * 128 + gd) * Sz + tin] = tile[tx][dh_loc];
    }
}

__global__ __launch_bounds__(256) void rmsnorm_kernel(
    const float* __restrict__ x, const float* __restrict__ w,
    __half* __restrict__ out, float* __restrict__ out_raw)
{
    const int row = blockIdx.x;
    const float* xr = x + (size_t)row * Dz;
    __half* orow = out + (size_t)row * Dz;
    const int tid = threadIdx.x;
    float ss = 0.f;
    #pragma unroll
    for (int i = tid*4; i < Dz; i += 1024) {
        float4 v = *(const float4*)(xr + i);
        ss += v.x*v.x + v.y*v.y + v.z*v.z + v.w*v.w;
    }
    __shared__ float red[256];
    red[tid] = ss; __syncthreads();
    for (int s = 128; s > 0; s >>= 1) { if (tid < s) red[tid] += red[tid+s]; __syncthreads(); }
    const float scale = rsqrtf(red[0] / (float)Dz + 1e-6f);
    #pragma unroll
    for (int i = tid*4; i < Dz; i += 1024) {
        float4 v = *(const float4*)(xr + i);
        float4 ww = *(const float4*)(w + i);
        float4 o;
        o.x = v.x*scale*ww.x; o.y = v.y*scale*ww.y;
        o.z = v.z*scale*ww.z; o.w = v.w*scale*ww.w;
        if (out_raw) *(float4*)(out_raw + (size_t)row * Dz + i) = o;
        *(half2*)(orow + i)     = __floats2half2_rn(o.x, o.y);
        *(half2*)(orow + i + 2) = __floats2half2_rn(o.z, o.w);
    }
}

__global__ __launch_bounds__(256) void rope_kernel16(__half* __restrict__ q, __half* __restrict__ k)
{
    const size_t idx = (size_t)blockIdx.x * 256 + threadIdx.x;
    if (idx >= (size_t)NTz * Hz * 64) return;
    const int    j    = (int)(idx & 63);
    const size_t th   = idx >> 6;
    const int    head = (int)(th & 15);
    const size_t tok  = th >> 4;
    const int    s    = (int)(tok & (Sz - 1));
    const double inv  = exp(-(double)(2*j) / 128.0 * 9.210340371976184);
    const double ang  = (double)s * inv;
    const float  c  = (float)cos(ang);
    const float  sn = (float)sin(ang);
    const size_t base = tok * (size_t)Dz + (size_t)head * DHz + j;
    float q1 = __half2float(q[base]), q2 = __half2float(q[base + 64]);
    q[base]      = __float2half_rn(q1*c - q2*sn);
    q[base + 64] = __float2half_rn(q2*c + q1*sn);
    float k1 = __half2float(k[base]), k2 = __half2float(k[base + 64]);
    k[base]      = __float2half_rn(k1*c - k2*sn);
    k[base + 64] = __float2half_rn(k2*c + k1*sn);
}

__global__ __launch_bounds__(256) void softmax_kernel16(__half* __restrict__ Ph, float* __restrict__ rowsum)
{
    const size_t row = blockIdx.x;
    const int sloc = (int)(row & (Sz - 1));
    const int len = ((sloc >> 7) + 1) << 7;
    __half* p = Ph + row * (size_t)Sz;
    const int tid = threadIdx.x;
    float m = -1e30f;
    for (int i = tid*8; i < len; i += 2048) {
        uint4 u = *(const uint4*)(p + i);
        const half2* hp = (const half2*)&u;
        #pragma unroll
        for (int q = 0; q < 4; q++){
            float2 f = __half22float2(hp[q]);
            m = fmaxf(m, fmaxf(f.x, f.y));
        }
    }
    __shared__ float red[256];
    red[tid] = m; __syncthreads();
    for (int s = 128; s > 0; s >>= 1) { if (tid < s) red[tid] = fmaxf(red[tid], red[tid+s]); __syncthreads(); }
    m = red[0];
    __syncthreads();
    float sum = 0.f;
    for (int i = tid*8; i < len; i += 2048) {
        uint4 u = *(const uint4*)(p + i);
        half2* hp = (half2*)&u;
        #pragma unroll
        for (int q = 0; q < 4; q++){
            float2 f = __half22float2(hp[q]);
            half2 e = __floats2half2_rn(expf(f.x - m), expf(f.y - m));
            float2 ef = __half22float2(e);
            sum += ef.x + ef.y;
            hp[q] = e;
        }
        *(uint4*)(p + i) = u;
    }
    red[tid] = sum; __syncthreads();
    for (int s = 128; s > 0; s >>= 1) { if (tid < s) red[tid] += red[tid+s]; __syncthreads(); }
    if (tid == 0) rowsum[row] = red[0];
}

__global__ __launch_bounds__(256) void router_kernel(
    const float* __restrict__ h, const float* __restrict__ rw,
    const float* __restrict__ rb, int* __restrict__ choice)
{
    const int t = blockIdx.x;
    const float* xr = h + (size_t)t * Dz;
    const int tid = threadIdx.x;
    float s0 = 0.f, s1 = 0.f;
    #pragma unroll
    for (int i = tid*4; i < Dz; i += 1024) {
        float4 v  = *(const float4*)(xr + i);
        float4 w0 = *(const float4*)(rw + i);
        float4 w1 = *(const float4*)(rw + Dz + i);
        s0 += v.x*w0.x + v.y*w0.y + v.z*w0.z + v.w*w0.w;
        s1 += v.x*w1.x + v.y*w1.y + v.z*w1.z + v.w*w1.w;
    }
    __shared__ float r0[256], r1[256];
    r0[tid] = s0; r1[tid] = s1; __syncthreads();
    for (int s = 128; s > 0; s >>= 1) {
        if (tid < s) { r0[tid] += r0[tid+s]; r1[tid] += r1[tid+s]; }
        __syncthreads();
    }
    if (tid == 0) {
        const float l0 = r0[0] + rb[0], l1 = r1[0] + rb[1];
        choice[t] = (l1 > l0) ? 1 : 0;
    }
}

__global__ __launch_bounds__(256) void act_kernel16(
    __half* __restrict__ gate, const __half* __restrict__ up,
    const int* __restrict__ choice, int e)
{
    const int f = blockIdx.x * 256 + threadIdx.x;
    if (f >= Fz) return;
    const int tok = blockIdx.y;
    const size_t idx = (size_t)tok * Fz + f;
    if (choice[tok] == e) {
        const float g = __half2float(gate[idx]);
        const float u = __half2float(up[idx]);
        gate[idx] = __float2half_rn((g / (1.f + expf(-g))) * u);
    } else {
        gate[idx] = __float2half_rn(0.f);
    }
}

// ================= launch =================
extern "C" void kernel_launch(void* const* d_in, const int* in_sizes, int n_in,
                              void* d_out, int out_size)
{
    const float* x    = (const float*)d_in[0];
    const float* ln1w = (const float*)d_in[1];
    const float* wq   = (const float*)d_in[2];
    const float* bq   = (const float*)d_in[3];
    const float* wk   = (const float*)d_in[4];
    const float* bk   = (const float*)d_in[5];
    const float* wv   = (const float*)d_in[6];
    const float* bv   = (const float*)d_in[7];
    const float* wo   = (const float*)d_in[8];
    const float* ln2w = (const float*)d_in[9];
    const float* e1g  = (const float*)d_in[10];
    const float* e1u  = (const float*)d_in[11];
    const float* e1d  = (const float*)d_in[12];
    const float* e2g  = (const float*)d_in[13];
    const float* e2u  = (const float*)d_in[14];
    const float* e2d  = (const float*)d_in[15];
    const float* rw   = (const float*)d_in[16];
    const float* rb   = (const float*)d_in[17];
    float* out = (float*)d_out;

    __half *h1h, *qh, *kh, *vh, *ctxh, *ph, *gateh, *gate2h, *uph, *wrh;
    float *h2, *h3raw, *rs;
    int* choice;
    cudaGetSymbolAddress((void**)&h1h,   g_h1h);
    cudaGetSymbolAddress((void**)&qh,    g_qh);
    cudaGetSymbolAddress((void**)&kh,    g_kh);
    cudaGetSymbolAddress((void**)&vh,    g_vh);
    cudaGetSymbolAddress((void**)&ctxh,  g_ctxh);
    cudaGetSymbolAddress((void**)&h2,    g_h2);
    cudaGetSymbolAddress((void**)&h3raw, g_h3raw);
    cudaGetSymbolAddress((void**)&ph,    g_ph);
    cudaGetSymbolAddress((void**)&rs,    g_rs);
    cudaGetSymbolAddress((void**)&gateh,  g_gateh);
    cudaGetSymbolAddress((void**)&gate2h, g_gate2h);
    cudaGetSymbolAddress((void**)&uph,    g_uph);
    cudaGetSymbolAddress((void**)&wrh,    g_wrh);
    cudaGetSymbolAddress((void**)&choice, g_choice);

    cudaFuncSetAttribute(h16_gemm_f16out, cudaFuncAttributeMaxDynamicSharedMemorySize, SMEM_BYTES);
    cudaFuncSetAttribute(h16_gemm_f32out, cudaFuncAttributeMaxDynamicSharedMemorySize, SMEM_BYTES);
    cudaFuncSetAttribute(h16_gemm_down2,  cudaFuncAttributeMaxDynamicSharedMemorySize, SMEM_BYTES);
    cudaFuncSetAttribute(h16_scores,      cudaFuncAttributeMaxDynamicSharedMemorySize, SMEM_BYTES);
    cudaFuncSetAttribute(h16_ctx,         cudaFuncAttributeMaxDynamicSharedMemorySize, SMEM_BYTES);

    // --- weight pre-rounding: 2 consolidated launches ---
    {   const int per8 = (Dz*Dz)/8;
        h16_round_multi<<<dim3(per8/256, 4), 256>>>(wq, wk, wv, wo, wo, wo, wrh + WR_Q, per8);
    }
    {   const int per8 = (Fz*Dz)/8;
        h16_round_multi<<<dim3(per8/256, 6), 256>>>(e1g, e1u, e1d, e2g, e2u, e2d, wrh + WR_E1G, per8);
    }

    // --- attention block ---
    rmsnorm_kernel<<<NTz, 256>>>(x, ln1w, h1h, nullptr);
    h16_gemm_f16out<<<dim3(Dz/128, NTz/128), 256, SMEM_BYTES>>>(h1h, wrh+WR_Q, qh, bq, NTz, Dz, Dz);
    h16_gemm_f16out<<<dim3(Dz/128, NTz/128), 256, SMEM_BYTES>>>(h1h, wrh+WR_K, kh, bk, NTz, Dz, Dz);
    h16_gemm_f16out<<<dim3(Dz/128, NTz/128), 256, SMEM_BYTES>>>(h1h, wrh+WR_V, vh, bv, NTz, Dz, Dz);
    rope_kernel16<<<(NTz*Hz*64)/256, 256>>>(qh, kh);
    h16_scores<<<dim3(Sz/128, Sz/128, BHz), 256, SMEM_BYTES>>>(qh, kh, ph);
    __half* vt = kh;   // kh's memory reused as transposed V after scores consumed it
    transpose_v16<<<dim3(Dz/32, NTz/32), 256>>>(vh, vt);
    softmax_kernel16<<<BHz*Sz, 256>>>(ph, rs);
    h16_ctx<<<dim3(1, Sz/128, BHz), 256, SMEM_BYTES>>>(ph, vt, rs, ctxh);
    h16_gemm_f32out<<<dim3(Dz/128, NTz/128), 256, SMEM_BYTES>>>(ctxh, wrh+WR_O, h2, x, NTz, Dz, Dz);

    // --- MoE block ---
    rmsnorm_kernel<<<NTz, 256>>>(h2, ln2w, h1h, h3raw);
    router_kernel<<<NTz, 256>>>(h3raw, rw, rb, choice);

    h16_gemm_f16out<<<dim3(Fz/128, NTz/128), 256, SMEM_BYTES>>>(h1h, wrh+WR_E1G, gateh,  nullptr, NTz, Fz, Dz);
    h16_gemm_f16out<<<dim3(Fz/128, NTz/128), 256, SMEM_BYTES>>>(h1h, wrh+WR_E1U, uph,    nullptr, NTz, Fz, Dz);
    act_kernel16<<<dim3((Fz+255)/256, NTz), 256>>>(gateh, uph, choice, 0);
    h16_gemm_f16out<<<dim3(Fz/128, NTz/128), 256, SMEM_BYTES>>>(h1h, wrh+WR_E2G, gate2h, nullptr, NTz, Fz, Dz);
    h16_gemm_f16out<<<dim3(Fz/128, NTz/128), 256, SMEM_BYTES>>>(h1h, wrh+WR_E2U, uph,    nullptr, NTz, Fz, Dz);
    act_kernel16<<<dim3((Fz+255)/256, NTz), 256>>>(gate2h, uph, choice, 1);
    h16_gemm_down2<<<dim3(Dz/128, NTz/128), 256, SMEM_BYTES>>>(gateh, wrh+WR_E1D, gate2h, wrh+WR_E2D,
                                                               out, h2, NTz, Dz, Fz);
}